// round 1
// baseline (speedup 1.0000x reference)
#include <cuda_runtime.h>
#include <math.h>

// Problem constants
#define NB 16     // batch
#define NO 64     // objects
#define NK 63     // O-1
#define NC 8      // C
#define NA 3      // A
#define SEG 128   // per-segment width
#define NI 640    // num_in
#define NAC 24    // A*C
#define WPAD 33   // float4 row stride for smem (132 words, conflict-avoiding)

// Scratch (device globals: no allocation allowed)
__device__ float g_DB[NB * NO * NK * 48];   // binary dot products: [..][0:24]=w_b0, [24:48]=w_b1
__device__ float g_DU[NB * NO * 48];        // unary dots: [0:24]=w_u0, [24:48]=w_u1
__device__ float g_DN[NB * NAC];            // nullary dots
__device__ float g_andbias[NAC];
__device__ float g_nullpart[NB * NO * NC];  // per-(b,i) max of conj[a=0]

// ---------------------------------------------------------------------------
// and_bias[ac] = thr - sum_k(w[ac][k]^2) * tanh(thr)
__global__ void kbias_kernel(const float* __restrict__ andk) {
    int t = threadIdx.x;
    if (t < NAC) {
        const float* w = andk + (size_t)t * NI;
        float s = 0.f;
        #pragma unroll 8
        for (int k = 0; k < NI; k++) { float v = w[k]; s += v * v; }
        g_andbias[t] = 0.2f - s * tanhf(0.2f);
    }
}

// ---------------------------------------------------------------------------
// Per-b: DU[b][o][0:48] = unary[b][o] . [w_u0 ; w_u1],  DN[b][ac] = nullary[b] . w_n[ac]
__global__ __launch_bounds__(256) void precompute_kernel(
    const float* __restrict__ nullary,
    const float* __restrict__ unary,
    const float* __restrict__ andk)
{
    extern __shared__ float4 sm[];
    float4* ws = sm;              // 48 x WPAD
    float4* rs = sm + 48 * WPAD;  // 64 x WPAD
    int b = blockIdx.x;
    int tid = threadIdx.x;

    const float4* andk4 = (const float4*)andk;   // row = 160 float4
    // weights: row wr: ac = wr%24, seg = wr/24 ; w_u0 at float 128 (f4 32), w_u1 at 256 (f4 64)
    for (int idx = tid; idx < 48 * 32; idx += 256) {
        int wr = idx >> 5, t = idx & 31;
        int ac = wr % NAC, seg = wr / NAC;
        ws[wr * WPAD + t] = __ldg(andk4 + ac * 160 + 32 + seg * 32 + t);
    }
    // rows: unary[b] = 64 x 128 floats = 2048 float4
    const float4* src = (const float4*)unary + (size_t)b * 2048;
    for (int idx = tid; idx < 64 * 32; idx += 256) {
        int r = idx >> 5, t = idx & 31;
        rs[r * WPAD + t] = __ldg(src + idx);
    }
    __syncthreads();

    int rg = tid >> 4;   // 0..15 -> rows rg*4..rg*4+3
    int cg = tid & 15;   // 0..15 -> cols cg*3..cg*3+2
    float acc[4][3] = {};
    const float4* rp = rs + (rg * 4) * WPAD;
    const float4* wp = ws + (cg * 3) * WPAD;
    #pragma unroll 4
    for (int k = 0; k < 32; k++) {
        float4 w0 = wp[k], w1 = wp[WPAD + k], w2 = wp[2 * WPAD + k];
        #pragma unroll
        for (int rr = 0; rr < 4; rr++) {
            float4 rv = rp[rr * WPAD + k];
            acc[rr][0] += rv.x * w0.x + rv.y * w0.y + rv.z * w0.z + rv.w * w0.w;
            acc[rr][1] += rv.x * w1.x + rv.y * w1.y + rv.z * w1.z + rv.w * w1.w;
            acc[rr][2] += rv.x * w2.x + rv.y * w2.y + rv.z * w2.z + rv.w * w2.w;
        }
    }
    float* out = g_DU + (size_t)b * NO * 48;
    #pragma unroll
    for (int rr = 0; rr < 4; rr++) {
        int r = rg * 4 + rr;
        #pragma unroll
        for (int cc = 0; cc < 3; cc++)
            out[r * 48 + cg * 3 + cc] = acc[rr][cc];
    }

    // DN: 24 dots of length 128 (L1/L2 hot)
    if (tid < NAC) {
        const float* w = andk + (size_t)tid * NI;  // w_n = [0:128]
        const float* nv = nullary + b * SEG;
        float s = 0.f;
        #pragma unroll 8
        for (int k = 0; k < SEG; k++) s += nv[k] * w[k];
        g_DN[b * NAC + tid] = s;
    }
}

// ---------------------------------------------------------------------------
// Main GEMM: DB[(b,i)][k][0:48] = binary[b][i][k] . [w_b0 ; w_b1]
// block = one (b,i): 63 rows (+1 pad), 48 cols, K=128
__global__ __launch_bounds__(256) void gemm_db_kernel(
    const float* __restrict__ binary,
    const float* __restrict__ andk)
{
    extern __shared__ float4 sm[];
    float4* ws = sm;              // 48 x WPAD
    float4* rs = sm + 48 * WPAD;  // 64 x WPAD
    int blk = blockIdx.x;         // b*64 + i
    int tid = threadIdx.x;

    const float4* andk4 = (const float4*)andk;
    // w_b0 at float 384 (f4 96), w_b1 at 512 (f4 128)
    for (int idx = tid; idx < 48 * 32; idx += 256) {
        int wr = idx >> 5, t = idx & 31;
        int ac = wr % NAC, seg = wr / NAC;
        ws[wr * WPAD + t] = __ldg(andk4 + ac * 160 + 96 + seg * 32 + t);
    }
    const float4* src = (const float4*)(binary + (size_t)blk * NK * SEG);
    for (int idx = tid; idx < 63 * 32; idx += 256) {
        int r = idx >> 5, t = idx & 31;
        rs[r * WPAD + t] = __ldg(src + idx);
    }
    for (int t = tid; t < 32; t += 256) rs[63 * WPAD + t] = make_float4(0.f, 0.f, 0.f, 0.f);
    __syncthreads();

    int rg = tid >> 4;
    int cg = tid & 15;
    float acc[4][3] = {};
    const float4* rp = rs + (rg * 4) * WPAD;
    const float4* wp = ws + (cg * 3) * WPAD;
    #pragma unroll 4
    for (int k = 0; k < 32; k++) {
        float4 w0 = wp[k], w1 = wp[WPAD + k], w2 = wp[2 * WPAD + k];
        #pragma unroll
        for (int rr = 0; rr < 4; rr++) {
            float4 rv = rp[rr * WPAD + k];
            acc[rr][0] += rv.x * w0.x + rv.y * w0.y + rv.z * w0.z + rv.w * w0.w;
            acc[rr][1] += rv.x * w1.x + rv.y * w1.y + rv.z * w1.z + rv.w * w1.w;
            acc[rr][2] += rv.x * w2.x + rv.y * w2.y + rv.z * w2.z + rv.w * w2.w;
        }
    }
    float* out = g_DB + (size_t)blk * NK * 48;
    #pragma unroll
    for (int rr = 0; rr < 4; rr++) {
        int r = rg * 4 + rr;
        if (r < NK) {
            #pragma unroll
            for (int cc = 0; cc < 3; cc++)
                out[r * 48 + cg * 3 + cc] = acc[rr][cc];
        }
    }
}

// ---------------------------------------------------------------------------
// Combine: per (b,i). thread k in [0,63): perm p=(i,j), j = k + (k>=i)
// s[ac] = andbias + DN + DU0[b,i] + DU1[b,j] + DB0[b,i,k] + DB1[b,j,i']
// conj = tanh(s); a=2 -> out2 directly; a=1 -> max over k -> out1; a=0 -> max -> partial
__global__ __launch_bounds__(64) void combine_kernel(
    const float* __restrict__ ork, float* __restrict__ out)
{
    __shared__ float base[NAC];
    __shared__ float red[64][16];
    int blk = blockIdx.x;
    int b = blk >> 6, i = blk & 63;
    int tid = threadIdx.x;

    if (tid < NAC)
        base[tid] = g_andbias[tid] + g_DN[b * NAC + tid] + g_DU[((size_t)b * NO + i) * 48 + tid];
    __syncthreads();

    bool act = (tid < NK);
    float tv[16];
    #pragma unroll
    for (int c = 0; c < 16; c++) tv[c] = -2.0f;

    if (act) {
        int k = tid;
        int j = k + (k >= i ? 1 : 0);
        int ip = (k < i) ? (i - 1) : i;
        const float* du1 = g_DU + ((size_t)b * NO + j) * 48 + 24;
        const float* db0 = g_DB + (((size_t)b * NO + i) * NK + k) * 48;
        const float* db1 = g_DB + (((size_t)b * NO + j) * NK + ip) * 48 + 24;

        #pragma unroll
        for (int ac = 0; ac < 16; ac++)
            tv[ac] = tanhf(base[ac] + du1[ac] + db0[ac] + db1[ac]);

        // a = 2: direct or-stage (no reduction)
        float ob2 = 0.f;
        #pragma unroll
        for (int c = 0; c < NC; c++) { float v = ork[16 + c]; ob2 += v * v; }
        float s2 = ob2 * tanhf(0.2f) - 0.2f;
        #pragma unroll
        for (int c = 0; c < NC; c++) {
            float t2 = tanhf(base[16 + c] + du1[16 + c] + db0[16 + c] + db1[16 + c]);
            s2 += t2 * ork[16 + c];
        }
        out[16 + NB * NO + (size_t)blk * NK + k] = s2;
    }

    #pragma unroll
    for (int c = 0; c < 16; c++) red[tid][c] = tv[c];
    __syncthreads();
    for (int off = 32; off > 0; off >>= 1) {
        if (tid < off) {
            #pragma unroll
            for (int c = 0; c < 16; c++)
                red[tid][c] = fmaxf(red[tid][c], red[tid + off][c]);
        }
        __syncthreads();
    }
    if (tid == 0) {
        float ob1 = 0.f;
        #pragma unroll
        for (int c = 0; c < NC; c++) { float v = ork[8 + c]; ob1 += v * v; }
        float s1 = ob1 * tanhf(0.2f) - 0.2f;
        #pragma unroll
        for (int c = 0; c < NC; c++) s1 += red[0][8 + c] * ork[8 + c];
        out[16 + blk] = s1;
    }
    if (tid < NC) g_nullpart[(b * NO + i) * NC + tid] = red[0][tid];
}

// ---------------------------------------------------------------------------
// Final null reduce: out0[b] = or-stage(max over i of nullpart)
__global__ __launch_bounds__(64) void finalnull_kernel(
    const float* __restrict__ ork, float* __restrict__ out)
{
    __shared__ float red[64][NC];
    int b = blockIdx.x;
    int tid = threadIdx.x;
    #pragma unroll
    for (int c = 0; c < NC; c++) red[tid][c] = g_nullpart[(b * NO + tid) * NC + c];
    __syncthreads();
    for (int off = 32; off > 0; off >>= 1) {
        if (tid < off) {
            #pragma unroll
            for (int c = 0; c < NC; c++)
                red[tid][c] = fmaxf(red[tid][c], red[tid + off][c]);
        }
        __syncthreads();
    }
    if (tid == 0) {
        float ob0 = 0.f;
        #pragma unroll
        for (int c = 0; c < NC; c++) { float v = ork[c]; ob0 += v * v; }
        float s0 = ob0 * tanhf(0.2f) - 0.2f;
        #pragma unroll
        for (int c = 0; c < NC; c++) s0 += red[0][c] * ork[c];
        out[b] = s0;
    }
}

// ---------------------------------------------------------------------------
extern "C" void kernel_launch(void* const* d_in, const int* in_sizes, int n_in,
                              void* d_out, int out_size)
{
    const float* nullary = (const float*)d_in[0];
    const float* unary   = (const float*)d_in[1];
    const float* binary  = (const float*)d_in[2];
    const float* andk    = (const float*)d_in[3];
    const float* ork     = (const float*)d_in[4];
    float* out = (float*)d_out;

    size_t smK = (size_t)(48 + 64) * WPAD * sizeof(float4);  // ~59 KB dynamic smem
    cudaFuncSetAttribute(precompute_kernel, cudaFuncAttributeMaxDynamicSharedMemorySize, (int)smK);
    cudaFuncSetAttribute(gemm_db_kernel,    cudaFuncAttributeMaxDynamicSharedMemorySize, (int)smK);

    kbias_kernel<<<1, 32>>>(andk);
    precompute_kernel<<<NB, 256, smK>>>(nullary, unary, andk);
    gemm_db_kernel<<<NB * NO, 256, smK>>>(binary, andk);
    combine_kernel<<<NB * NO, 64>>>(ork, out);
    finalnull_kernel<<<NB, 64>>>(ork, out);
}

// round 2
// speedup vs baseline: 1.2177x; 1.2177x over previous
#include <cuda_runtime.h>
#include <math.h>

// Problem constants
#define NB 16     // batch
#define NO 64     // objects
#define NK 63     // O-1
#define NC 8      // C
#define SEG 128   // per-segment width
#define NI 640    // num_in
#define NAC 24    // A*C
#define WPAD 33   // float4 row stride in smem (132 words)
#define THRv 0.2f
#define TTHR 0.19737532f   // tanh(0.2)

// Scratch (device globals: no allocation allowed)
__device__ float g_DB[NB * NO * NK * 48];   // binary dots: [0:24]=w_b0, [24:48]=w_b1
__device__ float g_DU[NB * NO * 48];        // unary dots:  [0:24]=w_u0, [24:48]=w_u1
__device__ float g_DN[NB * NAC];            // nullary dots
__device__ float g_andbias[NAC];
__device__ float g_orbias[3];
__device__ float g_nullpart[NB * NO * NC];

__device__ __forceinline__ float tanhapx(float x) {
    float y; asm("tanh.approx.f32 %0, %1;" : "=f"(y) : "f"(x)); return y;
}
__device__ __forceinline__ void ffma2(unsigned long long& d,
                                      unsigned long long a, unsigned long long b) {
    asm("fma.rn.f32x2 %0, %1, %2, %0;" : "+l"(d) : "l"(a), "l"(b));
}
__device__ __forceinline__ float f2sum(unsigned long long v) {
    float lo, hi; asm("mov.b64 {%0, %1}, %2;" : "=f"(lo), "=f"(hi) : "l"(v));
    return lo + hi;
}

// ---------------------------------------------------------------------------
// Setup: and_bias[24], or_bias[3], DN[b][ac]
__global__ __launch_bounds__(448) void setup_kernel(
    const float* __restrict__ nullary,
    const float* __restrict__ andk,
    const float* __restrict__ ork)
{
    int t = threadIdx.x;
    if (t < NAC) {
        const float* w = andk + (size_t)t * NI;
        float s = 0.f;
        #pragma unroll 8
        for (int k = 0; k < NI; k++) { float v = w[k]; s += v * v; }
        g_andbias[t] = THRv - s * TTHR;
    } else if (t < 27) {
        int a = t - 24;
        float s = 0.f;
        #pragma unroll
        for (int c = 0; c < NC; c++) { float v = ork[a * NC + c]; s += v * v; }
        g_orbias[a] = s * TTHR - THRv;
    } else if (t >= 32 && t < 32 + NB * NAC) {
        int idx = t - 32;
        int b = idx / NAC, ac = idx % NAC;
        const float* w = andk + (size_t)ac * NI;   // nullary segment = [0:128]
        const float* nv = nullary + b * SEG;
        float s = 0.f;
        #pragma unroll 8
        for (int k = 0; k < SEG; k++) s += nv[k] * w[k];
        g_DN[b * NAC + ac] = s;
    }
}

// ---------------------------------------------------------------------------
// Unified GEMM (f32x2 packed FFMA):
//   blocks [0, 1024):    DB[(b,i)][k][0:48] = binary[b][i][k] . [w_b0 ; w_b1]
//   blocks [1024, 1040): DU[b][o][0:48]     = unary[b][o]     . [w_u0 ; w_u1]
__global__ __launch_bounds__(256) void gemm_kernel(
    const float* __restrict__ binary,
    const float* __restrict__ unary,
    const float* __restrict__ andk)
{
    extern __shared__ float4 sm[];
    float4* ws = sm;              // 48 x WPAD (weights, float4 granules along K)
    float4* rs = sm + 48 * WPAD;  // 64 x WPAD (rows)
    int blk = blockIdx.x;
    int tid = threadIdx.x;
    bool isU = blk >= NB * NO;

    const float4* andk4 = (const float4*)andk;   // row of and_kernel = 160 float4
    int wbase = isU ? 32 : 96;                   // w_u0 at f4 32, w_b0 at f4 96
    for (int idx = tid; idx < 48 * 32; idx += 256) {
        int wr = idx >> 5, t = idx & 31;
        int ac = wr % NAC, seg = wr / NAC;
        ws[wr * WPAD + t] = __ldg(andk4 + ac * 160 + wbase + seg * 32 + t);
    }
    const float4* src = isU
        ? ((const float4*)unary  + (size_t)(blk - NB * NO) * 2048)
        : ((const float4*)binary + (size_t)blk * NK * 32);
    int nrows = isU ? 64 : NK;
    for (int idx = tid; idx < nrows * 32; idx += 256) {
        int r = idx >> 5, t = idx & 31;
        rs[r * WPAD + t] = __ldg(src + idx);
    }
    if (!isU)
        for (int t = tid; t < 32; t += 256) rs[63 * WPAD + t] = make_float4(0.f, 0.f, 0.f, 0.f);
    __syncthreads();

    int rg = tid >> 4;   // 16 row groups x 4 rows
    int cg = tid & 15;   // 16 col groups x 3 cols
    unsigned long long acc[4][3];
    #pragma unroll
    for (int r = 0; r < 4; r++)
        #pragma unroll
        for (int c = 0; c < 3; c++) acc[r][c] = 0ULL;

    // View smem as ulonglong2: .x packs floats (0,1), .y packs (2,3) of each float4
    const ulonglong2* rp = (const ulonglong2*)(rs + (rg * 4) * WPAD);
    const ulonglong2* wp = (const ulonglong2*)(ws + (cg * 3) * WPAD);
    #pragma unroll 4
    for (int k = 0; k < 32; k++) {
        ulonglong2 w0 = wp[k], w1 = wp[WPAD + k], w2 = wp[2 * WPAD + k];
        #pragma unroll
        for (int rr = 0; rr < 4; rr++) {
            ulonglong2 rv = rp[rr * WPAD + k];
            ffma2(acc[rr][0], rv.x, w0.x); ffma2(acc[rr][0], rv.y, w0.y);
            ffma2(acc[rr][1], rv.x, w1.x); ffma2(acc[rr][1], rv.y, w1.y);
            ffma2(acc[rr][2], rv.x, w2.x); ffma2(acc[rr][2], rv.y, w2.y);
        }
    }

    float* out = isU ? (g_DU + (size_t)(blk - NB * NO) * NO * 48)
                     : (g_DB + (size_t)blk * NK * 48);
    #pragma unroll
    for (int rr = 0; rr < 4; rr++) {
        int r = rg * 4 + rr;
        if (r < nrows) {
            #pragma unroll
            for (int cc = 0; cc < 3; cc++)
                out[r * 48 + cg * 3 + cc] = f2sum(acc[rr][cc]);
        }
    }
}

// ---------------------------------------------------------------------------
// Combine: block = (b,i); thread k in [0,63): perm p=(i,j), j = k + (k>=i)
__global__ __launch_bounds__(64) void combine_kernel(
    const float* __restrict__ ork, float* __restrict__ out)
{
    __shared__ float base[NAC];
    __shared__ float red[64][17];
    __shared__ float colmax[16];
    int blk = blockIdx.x;
    int b = blk >> 6, i = blk & 63;
    int tid = threadIdx.x;

    if (tid < NAC)
        base[tid] = g_andbias[tid] + g_DN[b * NAC + tid] + g_DU[((size_t)b * NO + i) * 48 + tid];
    __syncthreads();

    float tv[16];
    #pragma unroll
    for (int c = 0; c < 16; c++) tv[c] = -2.0f;

    if (tid < NK) {
        int k = tid;
        int j = k + (k >= i ? 1 : 0);
        int ip = (k < i) ? (i - 1) : i;
        const float4* du1 = (const float4*)(g_DU + ((size_t)b * NO + j) * 48 + 24);
        const float4* db0 = (const float4*)(g_DB + (((size_t)b * NO + i) * NK + k) * 48);
        const float4* db1 = (const float4*)(g_DB + (((size_t)b * NO + j) * NK + ip) * 48 + 24);

        float s[24];
        #pragma unroll
        for (int q = 0; q < 6; q++) {
            float4 u  = __ldg(du1 + q);
            float4 v0 = __ldg(db0 + q);
            float4 v1 = __ldg(db1 + q);
            s[4 * q + 0] = base[4 * q + 0] + u.x + v0.x + v1.x;
            s[4 * q + 1] = base[4 * q + 1] + u.y + v0.y + v1.y;
            s[4 * q + 2] = base[4 * q + 2] + u.z + v0.z + v1.z;
            s[4 * q + 3] = base[4 * q + 3] + u.w + v0.w + v1.w;
        }
        #pragma unroll
        for (int c = 0; c < 16; c++) tv[c] = tanhapx(s[c]);

        // a = 2: direct or-stage
        float s2 = g_orbias[2];
        #pragma unroll
        for (int c = 0; c < NC; c++) s2 += tanhapx(s[16 + c]) * __ldg(ork + 16 + c);
        out[16 + NB * NO + (size_t)blk * NK + k] = s2;
    }

    #pragma unroll
    for (int c = 0; c < 16; c++) red[tid][c] = tv[c];
    __syncthreads();
    if (tid < 16) {
        float m = red[0][tid];
        #pragma unroll 8
        for (int r = 1; r < 64; r++) m = fmaxf(m, red[r][tid]);
        colmax[tid] = m;
    }
    __syncthreads();
    if (tid == 0) {
        float s1 = g_orbias[1];
        #pragma unroll
        for (int c = 0; c < NC; c++) s1 += colmax[8 + c] * __ldg(ork + 8 + c);
        out[16 + blk] = s1;
    }
    if (tid < NC) g_nullpart[(b * NO + i) * NC + tid] = colmax[tid];
}

// ---------------------------------------------------------------------------
// Final null reduce: out0[b] = or-stage(max over i of nullpart)
__global__ __launch_bounds__(64) void finalnull_kernel(
    const float* __restrict__ ork, float* __restrict__ out)
{
    __shared__ float red[64][NC + 1];
    int b = blockIdx.x;
    int tid = threadIdx.x;
    #pragma unroll
    for (int c = 0; c < NC; c++) red[tid][c] = g_nullpart[(b * NO + tid) * NC + c];
    __syncthreads();
    if (tid < NC) {
        float m = red[0][tid];
        #pragma unroll 8
        for (int r = 1; r < 64; r++) m = fmaxf(m, red[r][tid]);
        red[0][tid] = m;
    }
    __syncthreads();
    if (tid == 0) {
        float s0 = g_orbias[0];
        #pragma unroll
        for (int c = 0; c < NC; c++) s0 += red[0][c] * __ldg(ork + c);
        out[b] = s0;
    }
}

// ---------------------------------------------------------------------------
extern "C" void kernel_launch(void* const* d_in, const int* in_sizes, int n_in,
                              void* d_out, int out_size)
{
    const float* nullary = (const float*)d_in[0];
    const float* unary   = (const float*)d_in[1];
    const float* binary  = (const float*)d_in[2];
    const float* andk    = (const float*)d_in[3];
    const float* ork     = (const float*)d_in[4];
    float* out = (float*)d_out;

    size_t smK = (size_t)(48 + 64) * WPAD * sizeof(float4);  // ~59 KB dynamic smem
    cudaFuncSetAttribute(gemm_kernel, cudaFuncAttributeMaxDynamicSharedMemorySize, (int)smK);

    setup_kernel<<<1, 448>>>(nullary, andk, ork);
    gemm_kernel<<<NB * NO + NB, 256, smK>>>(binary, unary, andk);
    combine_kernel<<<NB * NO, 64>>>(ork, out);
    finalnull_kernel<<<NB, 64>>>(ork, out);
}

// round 3
// speedup vs baseline: 1.6570x; 1.3607x over previous
#include <cuda_runtime.h>
#include <math.h>

// Problem constants
#define NB 16     // batch
#define NO 64     // objects
#define NK 63     // O-1
#define NC 8      // C
#define SEG 128   // per-segment width
#define NI 640    // num_in
#define NAC 24    // A*C
#define WPAD 33   // float4 row stride in smem (132 words)
#define THRv 0.2f
#define TTHR 0.19737532f   // tanh(0.2)

// Scratch (device globals: no allocation allowed)
__device__ float g_DB[NB * NO * NK * 48];   // binary dots: [0:24]=w_b0, [24:48]=w_b1
__device__ float g_DU[NB * NO * 48];        // unary dots:  [0:24]=w_u0, [24:48]=w_u1
__device__ float g_DN[NB * NAC];            // nullary dots
__device__ float g_andbias[NAC];
__device__ float g_orbias[3];
__device__ float g_nullpart[NB * NO * NC];
__device__ int   g_cnt[NB];                 // zero-init; self-resetting

__device__ __forceinline__ float tanhapx(float x) {
    float y; asm("tanh.approx.f32 %0, %1;" : "=f"(y) : "f"(x)); return y;
}
__device__ __forceinline__ void ffma2(unsigned long long& d,
                                      unsigned long long a, unsigned long long b) {
    asm("fma.rn.f32x2 %0, %1, %2, %0;" : "+l"(d) : "l"(a), "l"(b));
}
__device__ __forceinline__ float f2sum(unsigned long long v) {
    float lo, hi; asm("mov.b64 {%0, %1}, %2;" : "=f"(lo), "=f"(hi) : "l"(v));
    return lo + hi;
}

// ---------------------------------------------------------------------------
// Unified GEMM + setup:
//   blocks [0, 1024):    DB[(b,i)][k][0:48] = binary[b][i][k] . [w_b0 ; w_b1]
//   blocks [1024, 1040): DU[b][o][0:48]     = unary[b][o]     . [w_u0 ; w_u1]
//   block  1040:         and_bias[24], or_bias[3]
//   block  1041:         DN[b][ac]  (384 dots of length 128)
__global__ __launch_bounds__(256) void gemm_kernel(
    const float* __restrict__ binary,
    const float* __restrict__ unary,
    const float* __restrict__ nullary,
    const float* __restrict__ andk,
    const float* __restrict__ ork)
{
    extern __shared__ float4 sm[];
    int blk = blockIdx.x;
    int tid = threadIdx.x;

    if (blk >= NB * NO + NB) {
        if (blk == NB * NO + NB) {
            // and_bias: 24 rows x 8 partial sums of 80 elements
            __shared__ float sred[NAC][8];
            if (tid < 192) {
                int row = tid >> 3, part = tid & 7;
                const float* w = andk + (size_t)row * NI + part * 80;
                float s = 0.f;
                #pragma unroll 8
                for (int k = 0; k < 80; k++) { float v = w[k]; s += v * v; }
                sred[row][part] = s;
            }
            __syncthreads();
            if (tid < NAC) {
                float s = 0.f;
                #pragma unroll
                for (int p = 0; p < 8; p++) s += sred[tid][p];
                g_andbias[tid] = THRv - s * TTHR;
            } else if (tid < 27) {
                int a = tid - NAC;
                float s = 0.f;
                #pragma unroll
                for (int c = 0; c < NC; c++) { float v = ork[a * NC + c]; s += v * v; }
                g_orbias[a] = s * TTHR - THRv;
            }
        } else {
            // DN: 384 dots (b,ac), each length 128
            for (int d = tid; d < NB * NAC; d += 256) {
                int b = d / NAC, ac = d % NAC;
                const float* w = andk + (size_t)ac * NI;
                const float* nv = nullary + b * SEG;
                float s = 0.f;
                #pragma unroll 8
                for (int k = 0; k < SEG; k++) s += nv[k] * w[k];
                g_DN[d] = s;
            }
        }
        return;
    }

    float4* ws = sm;              // 48 x WPAD (weights)
    float4* rs = sm + 48 * WPAD;  // 64 x WPAD (rows)
    bool isU = blk >= NB * NO;

    const float4* andk4 = (const float4*)andk;   // row of and_kernel = 160 float4
    int wbase = isU ? 32 : 96;                   // w_u0 at f4 32, w_b0 at f4 96
    for (int idx = tid; idx < 48 * 32; idx += 256) {
        int wr = idx >> 5, t = idx & 31;
        int ac = wr % NAC, seg = wr / NAC;
        ws[wr * WPAD + t] = __ldg(andk4 + ac * 160 + wbase + seg * 32 + t);
    }
    const float4* src = isU
        ? ((const float4*)unary  + (size_t)(blk - NB * NO) * 2048)
        : ((const float4*)binary + (size_t)blk * NK * 32);
    int nrows = isU ? 64 : NK;
    for (int idx = tid; idx < nrows * 32; idx += 256) {
        int r = idx >> 5, t = idx & 31;
        rs[r * WPAD + t] = __ldg(src + idx);
    }
    if (!isU)
        for (int t = tid; t < 32; t += 256) rs[63 * WPAD + t] = make_float4(0.f, 0.f, 0.f, 0.f);
    __syncthreads();

    int rg = tid >> 4;   // 16 row groups x 4 rows
    int cg = tid & 15;   // 16 col groups x 3 cols
    unsigned long long acc[4][3];
    #pragma unroll
    for (int r = 0; r < 4; r++)
        #pragma unroll
        for (int c = 0; c < 3; c++) acc[r][c] = 0ULL;

    const ulonglong2* rp  = (const ulonglong2*)(rs + (rg * 4) * WPAD);
    const ulonglong2* wp0 = (const ulonglong2*)(ws + (cg * 3) * WPAD);
    const ulonglong2* wp1 = wp0 + WPAD;
    const ulonglong2* wp2 = wp1 + WPAD;
    #pragma unroll 2
    for (int k = 0; k < 32; k++) {
        ulonglong2 w0 = wp0[k], w1 = wp1[k], w2 = wp2[k];
        #pragma unroll
        for (int rr = 0; rr < 4; rr++) {
            ulonglong2 rv = rp[rr * WPAD + k];
            ffma2(acc[rr][0], rv.x, w0.x); ffma2(acc[rr][0], rv.y, w0.y);
            ffma2(acc[rr][1], rv.x, w1.x); ffma2(acc[rr][1], rv.y, w1.y);
            ffma2(acc[rr][2], rv.x, w2.x); ffma2(acc[rr][2], rv.y, w2.y);
        }
    }

    float* out = isU ? (g_DU + (size_t)(blk - NB * NO) * NO * 48)
                     : (g_DB + (size_t)blk * NK * 48);
    #pragma unroll
    for (int rr = 0; rr < 4; rr++) {
        int r = rg * 4 + rr;
        if (r < nrows) {
            #pragma unroll
            for (int cc = 0; cc < 3; cc++)
                out[r * 48 + cg * 3 + cc] = f2sum(acc[rr][cc]);
        }
    }
}

// ---------------------------------------------------------------------------
// Combine: block handles 4 (b,i) tiles (all same b). Per tile: 64 threads,
// thread k in [0,63): perm p=(i,j), j = k + (k>=i). Fused final-null reduce.
__global__ __launch_bounds__(256) void combine_kernel(
    const float* __restrict__ ork, float* __restrict__ out)
{
    __shared__ float base[4][NAC];
    __shared__ float red[4][64][17];
    __shared__ float colmax[4][16];
    __shared__ int isLast;

    int blk  = blockIdx.x;          // 0..255
    int tile = threadIdx.x >> 6;    // 0..3
    int tid  = threadIdx.x & 63;
    int gi = blk * 4 + tile;        // (b,i) flat index
    int b = gi >> 6, i = gi & 63;

    if (tid < NAC)
        base[tile][tid] = g_andbias[tid] + g_DN[b * NAC + tid]
                        + g_DU[((size_t)b * NO + i) * 48 + tid];
    __syncthreads();

    float tv[16];
    #pragma unroll
    for (int c = 0; c < 16; c++) tv[c] = -2.0f;

    if (tid < NK) {
        int k = tid;
        int j = k + (k >= i ? 1 : 0);
        int ip = (k < i) ? (i - 1) : i;
        const float4* du1 = (const float4*)(g_DU + ((size_t)b * NO + j) * 48 + 24);
        const float4* db0 = (const float4*)(g_DB + (((size_t)b * NO + i) * NK + k) * 48);
        const float4* db1 = (const float4*)(g_DB + (((size_t)b * NO + j) * NK + ip) * 48 + 24);

        float s[24];
        #pragma unroll
        for (int q = 0; q < 6; q++) {
            float4 u  = __ldg(du1 + q);
            float4 v0 = __ldg(db0 + q);
            float4 v1 = __ldg(db1 + q);
            s[4 * q + 0] = base[tile][4 * q + 0] + u.x + v0.x + v1.x;
            s[4 * q + 1] = base[tile][4 * q + 1] + u.y + v0.y + v1.y;
            s[4 * q + 2] = base[tile][4 * q + 2] + u.z + v0.z + v1.z;
            s[4 * q + 3] = base[tile][4 * q + 3] + u.w + v0.w + v1.w;
        }
        #pragma unroll
        for (int c = 0; c < 16; c++) tv[c] = tanhapx(s[c]);

        // a = 2: direct or-stage
        float s2 = g_orbias[2];
        #pragma unroll
        for (int c = 0; c < NC; c++) s2 += tanhapx(s[16 + c]) * __ldg(ork + 16 + c);
        out[16 + NB * NO + (size_t)gi * NK + k] = s2;
    }

    #pragma unroll
    for (int c = 0; c < 16; c++) red[tile][tid][c] = tv[c];
    __syncthreads();
    if (tid < 16) {
        float m = red[tile][0][tid];
        #pragma unroll 8
        for (int r = 1; r < 64; r++) m = fmaxf(m, red[tile][r][tid]);
        colmax[tile][tid] = m;
    }
    __syncthreads();
    if (tid == 0) {
        float s1 = g_orbias[1];
        #pragma unroll
        for (int c = 0; c < NC; c++) s1 += colmax[tile][8 + c] * __ldg(ork + 8 + c);
        out[16 + gi] = s1;
    }
    if (tid < NC) g_nullpart[gi * NC + tid] = colmax[tile][tid];

    // Fused final null reduce: last of the 16 blocks for this b does it.
    __syncthreads();
    if (threadIdx.x == 0) {
        __threadfence();
        int v = atomicAdd(&g_cnt[b], 1);
        isLast = (v == 15) ? 1 : 0;
    }
    __syncthreads();
    if (isLast) {
        __threadfence();
        if (threadIdx.x < NC) {
            int c = threadIdx.x;
            float m = -2.0f;
            #pragma unroll 8
            for (int r = 0; r < NO; r++)
                m = fmaxf(m, g_nullpart[(b * NO + r) * NC + c]);
            colmax[0][c] = m;
        }
        __syncthreads();
        if (threadIdx.x == 0) {
            float s0 = g_orbias[0];
            #pragma unroll
            for (int c = 0; c < NC; c++) s0 += colmax[0][c] * __ldg(ork + c);
            out[b] = s0;
            g_cnt[b] = 0;   // reset for next graph replay
        }
    }
}

// ---------------------------------------------------------------------------
extern "C" void kernel_launch(void* const* d_in, const int* in_sizes, int n_in,
                              void* d_out, int out_size)
{
    const float* nullary = (const float*)d_in[0];
    const float* unary   = (const float*)d_in[1];
    const float* binary  = (const float*)d_in[2];
    const float* andk    = (const float*)d_in[3];
    const float* ork     = (const float*)d_in[4];
    float* out = (float*)d_out;

    size_t smK = (size_t)(48 + 64) * WPAD * sizeof(float4);  // ~59 KB dynamic smem
    cudaFuncSetAttribute(gemm_kernel, cudaFuncAttributeMaxDynamicSharedMemorySize, (int)smK);

    gemm_kernel<<<NB * NO + NB + 2, 256, smK>>>(binary, unary, nullary, andk, ork);
    combine_kernel<<<NB * NO / 4, 256>>>(ork, out);
}

// round 4
// speedup vs baseline: 1.6878x; 1.0186x over previous
#include <cuda_runtime.h>
#include <math.h>

// Problem constants
#define NB 16     // batch
#define NO 64     // objects
#define NK 63     // O-1
#define NC 8      // C
#define SEG 128   // per-segment width
#define NI 640    // num_in
#define NAC 24    // A*C
#define WPAD 33   // float4 row stride in smem (132 words)
#define THRv 0.2f
#define TTHR 0.19737532f   // tanh(0.2)

// Scratch (device globals: no allocation allowed)
__device__ float g_DB[NB * NO * NK * 48];   // binary dots: [0:24]=w_b0, [24:48]=w_b1
__device__ float g_DU[NB * NO * 48];        // unary dots:  [0:24]=w_u0, [24:48]=w_u1
__device__ float g_DN[NB * NAC];            // nullary dots
__device__ float g_andbias[NAC];
__device__ float g_orbias[3];
__device__ float g_nullpart[NB * NO * NC];
__device__ int   g_cnt[NB];                 // zero-init; self-resetting

__device__ __forceinline__ float tanhapx(float x) {
    float y; asm("tanh.approx.f32 %0, %1;" : "=f"(y) : "f"(x)); return y;
}
__device__ __forceinline__ void ffma2(unsigned long long& d,
                                      unsigned long long a, unsigned long long b) {
    asm("fma.rn.f32x2 %0, %1, %2, %0;" : "+l"(d) : "l"(a), "l"(b));
}
__device__ __forceinline__ float f2sum(unsigned long long v) {
    float lo, hi; asm("mov.b64 {%0, %1}, %2;" : "=f"(lo), "=f"(hi) : "l"(v));
    return lo + hi;
}

// ---------------------------------------------------------------------------
// Unified GEMM + setup (128 threads/block):
//   blocks [0, 1024):    DB[(b,i)][k][0:48] = binary[b][i][k] . [w_b0 ; w_b1]
//   blocks [1024, 1040): DU[b][o][0:48]     = unary[b][o]     . [w_u0 ; w_u1]
//   block  1040:         and_bias[24], or_bias[3]
//   block  1041:         DN[b][ac]
__global__ __launch_bounds__(128) void gemm_kernel(
    const float* __restrict__ binary,
    const float* __restrict__ unary,
    const float* __restrict__ nullary,
    const float* __restrict__ andk,
    const float* __restrict__ ork)
{
    extern __shared__ float4 sm[];
    int blk = blockIdx.x;
    int tid = threadIdx.x;

    if (blk >= NB * NO + NB) {
        if (blk == NB * NO + NB) {
            // and_bias: 24 rows x 4 partial sums of 160 elements
            __shared__ float sred[NAC][4];
            if (tid < 96) {
                int row = tid >> 2, part = tid & 3;
                const float* w = andk + (size_t)row * NI + part * 160;
                float s = 0.f;
                #pragma unroll 8
                for (int k = 0; k < 160; k++) { float v = w[k]; s += v * v; }
                sred[row][part] = s;
            }
            __syncthreads();
            if (tid < NAC) {
                float s = sred[tid][0] + sred[tid][1] + sred[tid][2] + sred[tid][3];
                g_andbias[tid] = THRv - s * TTHR;
            } else if (tid < 27) {
                int a = tid - NAC;
                float s = 0.f;
                #pragma unroll
                for (int c = 0; c < NC; c++) { float v = ork[a * NC + c]; s += v * v; }
                g_orbias[a] = s * TTHR - THRv;
            }
        } else {
            // DN: 384 dots (b,ac), each length 128
            for (int d = tid; d < NB * NAC; d += 128) {
                int b = d / NAC, ac = d % NAC;
                const float* w = andk + (size_t)ac * NI;
                const float* nv = nullary + b * SEG;
                float s = 0.f;
                #pragma unroll 8
                for (int k = 0; k < SEG; k++) s += nv[k] * w[k];
                g_DN[d] = s;
            }
        }
        return;
    }

    float4* ws = sm;              // 48 x WPAD (weights)
    float4* rs = sm + 48 * WPAD;  // 64 x WPAD (rows)
    bool isU = blk >= NB * NO;

    const float4* andk4 = (const float4*)andk;   // row of and_kernel = 160 float4
    int wbase = isU ? 32 : 96;                   // w_u0 at f4 32, w_b0 at f4 96
    for (int idx = tid; idx < 48 * 32; idx += 128) {
        int wr = idx >> 5, t = idx & 31;
        int ac = wr % NAC, seg = wr / NAC;
        ws[wr * WPAD + t] = __ldg(andk4 + ac * 160 + wbase + seg * 32 + t);
    }
    const float4* src = isU
        ? ((const float4*)unary  + (size_t)(blk - NB * NO) * 2048)
        : ((const float4*)binary + (size_t)blk * NK * 32);
    int nrows = isU ? 64 : NK;
    for (int idx = tid; idx < nrows * 32; idx += 128) {
        int r = idx >> 5, t = idx & 31;
        rs[r * WPAD + t] = __ldg(src + idx);
    }
    if (!isU)
        for (int t = tid; t < 32; t += 128) rs[63 * WPAD + t] = make_float4(0.f, 0.f, 0.f, 0.f);
    __syncthreads();

    int rg = tid >> 4;   // 8 row groups x 8 rows
    int cg = tid & 15;   // 16 col groups x 3 cols
    unsigned long long acc[8][3];
    #pragma unroll
    for (int r = 0; r < 8; r++)
        #pragma unroll
        for (int c = 0; c < 3; c++) acc[r][c] = 0ULL;

    const ulonglong2* rp  = (const ulonglong2*)(rs + (rg * 8) * WPAD);
    const ulonglong2* wp0 = (const ulonglong2*)(ws + (cg * 3) * WPAD);
    const ulonglong2* wp1 = wp0 + WPAD;
    const ulonglong2* wp2 = wp1 + WPAD;
    #pragma unroll 2
    for (int k = 0; k < 32; k++) {
        ulonglong2 w0 = wp0[k], w1 = wp1[k], w2 = wp2[k];
        #pragma unroll
        for (int rr = 0; rr < 8; rr++) {
            ulonglong2 rv = rp[rr * WPAD + k];
            ffma2(acc[rr][0], rv.x, w0.x); ffma2(acc[rr][0], rv.y, w0.y);
            ffma2(acc[rr][1], rv.x, w1.x); ffma2(acc[rr][1], rv.y, w1.y);
            ffma2(acc[rr][2], rv.x, w2.x); ffma2(acc[rr][2], rv.y, w2.y);
        }
    }

    float* out = isU ? (g_DU + (size_t)(blk - NB * NO) * NO * 48)
                     : (g_DB + (size_t)blk * NK * 48);
    #pragma unroll
    for (int rr = 0; rr < 8; rr++) {
        int r = rg * 8 + rr;
        if (r < nrows) {
            #pragma unroll
            for (int cc = 0; cc < 3; cc++)
                out[r * 48 + cg * 3 + cc] = f2sum(acc[rr][cc]);
        }
    }
}

// ---------------------------------------------------------------------------
// Combine: block = 2 tiles x 128 threads. Per tile: thread = (half, k),
// half 0 handles cols 0..11, half 1 handles cols 12..23 (reduce 12-15 + a=2 out).
// perm p=(i,j), j = k + (k>=i). Fused final-null reduce via atomic counter.
__global__ __launch_bounds__(256) void combine_kernel(
    const float* __restrict__ ork, float* __restrict__ out)
{
    __shared__ float base[2][NAC];
    __shared__ float red[2][64][17];
    __shared__ float colmax[2][16];
    __shared__ int isLast;

    int blk  = blockIdx.x;          // 0..511
    int tile = threadIdx.x >> 7;    // 0..1
    int tid  = threadIdx.x & 127;
    int k    = tid & 63;
    int half = tid >> 6;
    int gi = blk * 2 + tile;        // (b,i) flat index
    int b = gi >> 6, i = gi & 63;

    if (tid < NAC)
        base[tile][tid] = g_andbias[tid] + g_DN[b * NAC + tid]
                        + g_DU[((size_t)b * NO + i) * 48 + tid];
    __syncthreads();

    int j = k + (k >= i ? 1 : 0);
    int ip = (k < i) ? (i - 1) : i;
    const float4* du1 = (const float4*)(g_DU + ((size_t)b * NO + j) * 48 + 24) + half * 3;
    const float4* db0 = (const float4*)(g_DB + (((size_t)b * NO + i) * NK + k) * 48) + half * 3;
    const float4* db1 = (const float4*)(g_DB + (((size_t)b * NO + j) * NK + ip) * 48 + 24) + half * 3;

    float s[12];
    bool act = (k < NK);
    if (act) {
        #pragma unroll
        for (int q = 0; q < 3; q++) {
            float4 u  = __ldg(du1 + q);
            float4 v0 = __ldg(db0 + q);
            float4 v1 = __ldg(db1 + q);
            int cb = half * 12 + 4 * q;
            s[4 * q + 0] = base[tile][cb + 0] + u.x + v0.x + v1.x;
            s[4 * q + 1] = base[tile][cb + 1] + u.y + v0.y + v1.y;
            s[4 * q + 2] = base[tile][cb + 2] + u.z + v0.z + v1.z;
            s[4 * q + 3] = base[tile][cb + 3] + u.w + v0.w + v1.w;
        }
    }

    if (half == 0) {
        // reduce cols 0..11
        #pragma unroll
        for (int c = 0; c < 12; c++)
            red[tile][k][c] = act ? tanhapx(s[c]) : -2.0f;
    } else {
        // reduce cols 12..15
        #pragma unroll
        for (int c = 0; c < 4; c++)
            red[tile][k][12 + c] = act ? tanhapx(s[c]) : -2.0f;
        // a=2 or-stage: cols 16..23 = s[4..11]
        if (act) {
            float s2 = g_orbias[2];
            #pragma unroll
            for (int c = 0; c < NC; c++) s2 += tanhapx(s[4 + c]) * __ldg(ork + 16 + c);
            out[16 + NB * NO + (size_t)gi * NK + k] = s2;
        }
    }

    __syncthreads();
    if (tid < 16) {
        float m = red[tile][0][tid];
        #pragma unroll 8
        for (int r = 1; r < 64; r++) m = fmaxf(m, red[tile][r][tid]);
        colmax[tile][tid] = m;
    }
    __syncthreads();
    if (tid == 0) {
        float s1 = g_orbias[1];
        #pragma unroll
        for (int c = 0; c < NC; c++) s1 += colmax[tile][8 + c] * __ldg(ork + 8 + c);
        out[16 + gi] = s1;
    }
    if (tid < NC) g_nullpart[gi * NC + tid] = colmax[tile][tid];

    // Fused final-null reduce: last of the 32 blocks for this b does it.
    __syncthreads();
    if (threadIdx.x == 0) {
        __threadfence();
        int v = atomicAdd(&g_cnt[b], 1);
        isLast = (v == 31) ? 1 : 0;
    }
    __syncthreads();
    if (isLast) {
        __threadfence();
        if (threadIdx.x < NC) {
            int c = threadIdx.x;
            float m = -2.0f;
            #pragma unroll 8
            for (int r = 0; r < NO; r++)
                m = fmaxf(m, g_nullpart[(b * NO + r) * NC + c]);
            colmax[0][c] = m;
        }
        __syncthreads();
        if (threadIdx.x == 0) {
            float s0 = g_orbias[0];
            #pragma unroll
            for (int c = 0; c < NC; c++) s0 += colmax[0][c] * __ldg(ork + c);
            out[b] = s0;
            g_cnt[b] = 0;   // reset for next graph replay
        }
    }
}

// ---------------------------------------------------------------------------
extern "C" void kernel_launch(void* const* d_in, const int* in_sizes, int n_in,
                              void* d_out, int out_size)
{
    const float* nullary = (const float*)d_in[0];
    const float* unary   = (const float*)d_in[1];
    const float* binary  = (const float*)d_in[2];
    const float* andk    = (const float*)d_in[3];
    const float* ork     = (const float*)d_in[4];
    float* out = (float*)d_out;

    size_t smK = (size_t)(48 + 64) * WPAD * sizeof(float4);  // ~59 KB dynamic smem
    cudaFuncSetAttribute(gemm_kernel, cudaFuncAttributeMaxDynamicSharedMemorySize, (int)smK);

    gemm_kernel<<<NB * NO + NB + 2, 128, smK>>>(binary, unary, nullary, andk, ork);
    combine_kernel<<<NB * NO / 2, 256>>>(ork, out);
}